// round 8
// baseline (speedup 1.0000x reference)
#include <cuda_runtime.h>
#include <cuda_fp16.h>
#include <stdint.h>

// ---------------------------------------------------------------------------
// tcnn HashGrid encode: coords [N,3] in [0,1], table [16, 2^19, 2] f32.
// Output [N, 32] f32. Levels 0-4 dense, 5-15 spatial-hashed.
//
// R8: fp16 hashed table + 16B group loads. Hashed levels converted per
// launch to scaled (x4096) fp16x2 entries (4B). An aligned LDG.128 covers 4
// consecutive entries; since PRIME_x==1, the dx=1 corner index is
// f = e ^ (gx^(gx+1)), which lands in the SAME 16B group whenever
// (gx&3)!=3 (75% of points). Avg wavefronts/pt/lvl: 6 -> 5.
// Dense levels unchanged: repacked f32 64B cell records, quad-lane LDG.128.
// ---------------------------------------------------------------------------

namespace {
constexpr int      NLV    = 16;
constexpr int      NDENSE = 5;
constexpr int      NHASH  = 11;
constexpr unsigned TSZ    = 1u << 19;
constexpr unsigned TMASK  = TSZ - 1u;
constexpr unsigned PRIME2 = 2654435761u;
constexpr unsigned PRIME3 = 805459861u;
constexpr int      PTS    = 64;            // points per block
constexpr float    FSCL   = 4096.0f;       // fp16 storage scale
constexpr float    FINV   = 1.0f / 4096.0f;

constexpr double spow(int l) {
    double v = 1.0;
    for (int i = 0; i < l; ++i) v *= 1.4472692012786865;
    return v;
}
constexpr double scaled(int l) { return 16.0 * spow(l) - 1.0; }
constexpr unsigned resd(int l) {
    double sc = scaled(l);
    unsigned f = (unsigned)sc;
    return f + (((double)f < sc) ? 1u : 0u) + 1u;
}
constexpr unsigned cells_below(int l) {
    unsigned o = 0;
    for (int i = 0; i < l; ++i) o += resd(i) * resd(i) * resd(i);
    return o;
}
constexpr unsigned TOTAL_CELLS = cells_below(NDENSE);
static_assert(resd(0) == 16 && resd(4) == 71, "dense res sanity");
static_assert((unsigned long long)resd(4)*resd(4)*resd(4) <= TSZ, "lvl4 dense");
static_assert((unsigned long long)resd(5)*resd(5)*resd(5) >  TSZ, "lvl5 hashed");
static_assert(TOTAL_CELLS == 532784u, "cell count");
}

__constant__ float    c_scale[NLV] = {
    (float)scaled(0),(float)scaled(1),(float)scaled(2),(float)scaled(3),
    (float)scaled(4),(float)scaled(5),(float)scaled(6),(float)scaled(7),
    (float)scaled(8),(float)scaled(9),(float)scaled(10),(float)scaled(11),
    (float)scaled(12),(float)scaled(13),(float)scaled(14),(float)scaled(15)};
__constant__ unsigned c_res[NDENSE]  = {resd(0),resd(1),resd(2),resd(3),resd(4)};
__constant__ unsigned c_res2[NDENSE] = {resd(0)*resd(0),resd(1)*resd(1),
    resd(2)*resd(2),resd(3)*resd(3),resd(4)*resd(4)};
__constant__ unsigned c_coff[NDENSE] = {cells_below(0),cells_below(1),
    cells_below(2),cells_below(3),cells_below(4)};

__device__ __align__(128) float4   g_cells[(size_t)TOTAL_CELLS * 4];
__device__ __align__(128) unsigned g_half[(size_t)NHASH << 19];  // fp16x2 entries

// --- convert hashed levels to scaled fp16x2 (4 entries per thread).
__global__ void hg_to_half(const float2* __restrict__ table) {
    const unsigned n = (unsigned)NHASH << 19;
    const unsigned i = (blockIdx.x * blockDim.x + threadIdx.x) * 4u;
    if (i >= n) return;
    const float2* __restrict__ src = table + ((size_t)NDENSE << 19);
    uint4 o;
    {
        const float2 v = src[i + 0];
        const __half2 h = __floats2half2_rn(v.x * FSCL, v.y * FSCL);
        o.x = *reinterpret_cast<const unsigned*>(&h);
    }
    {
        const float2 v = src[i + 1];
        const __half2 h = __floats2half2_rn(v.x * FSCL, v.y * FSCL);
        o.y = *reinterpret_cast<const unsigned*>(&h);
    }
    {
        const float2 v = src[i + 2];
        const __half2 h = __floats2half2_rn(v.x * FSCL, v.y * FSCL);
        o.z = *reinterpret_cast<const unsigned*>(&h);
    }
    {
        const float2 v = src[i + 3];
        const __half2 h = __floats2half2_rn(v.x * FSCL, v.y * FSCL);
        o.w = *reinterpret_cast<const unsigned*>(&h);
    }
    *reinterpret_cast<uint4*>(g_half + i) = o;
}

// --- repack dense levels: cell (gx,gy,gz) -> 4 float4 = 8 corners (64B).
__global__ void hg_repack(const float2* __restrict__ table) {
    unsigned cid = blockIdx.x * blockDim.x + threadIdx.x;
    if (cid >= TOTAL_CELLS) return;

    int l = 0;
    #pragma unroll
    for (int i = 1; i < NDENSE; ++i) if (cid >= c_coff[i]) l = i;
    const unsigned res = c_res[l], res2 = c_res2[l];
    const unsigned local = cid - c_coff[l];
    const unsigned gz  = local / res2;
    const unsigned rem = local - gz * res2;
    const unsigned gy  = rem / res;
    const unsigned gx  = rem - gy * res;

    const unsigned R1  = res - 1u;
    const unsigned cx0 = gx,          cx1 = min(gx + 1u, R1);
    const unsigned cy0 = gy * res,    cy1 = min(gy + 1u, R1) * res;
    const unsigned cz0 = gz * res2,   cz1 = min(gz + 1u, R1) * res2;

    const float2* __restrict__ tbl = table + (size_t)l * (size_t)TSZ;
    float4* dst = &g_cells[(size_t)cid * 4];
    { float2 a = tbl[cx0+cy0+cz0], b = tbl[cx0+cy0+cz1]; dst[0]=make_float4(a.x,a.y,b.x,b.y); }
    { float2 a = tbl[cx0+cy1+cz0], b = tbl[cx0+cy1+cz1]; dst[1]=make_float4(a.x,a.y,b.x,b.y); }
    { float2 a = tbl[cx1+cy0+cz0], b = tbl[cx1+cy0+cz1]; dst[2]=make_float4(a.x,a.y,b.x,b.y); }
    { float2 a = tbl[cx1+cy1+cz0], b = tbl[cx1+cy1+cz1]; dst[3]=make_float4(a.x,a.y,b.x,b.y); }
}

// extract 32-bit word k (0..3) from a uint4
__device__ __forceinline__ unsigned ext4(const uint4& q, unsigned k) {
    return (k & 2u) ? ((k & 1u) ? q.w : q.z) : ((k & 1u) ? q.y : q.x);
}

// --- main encode. Block = 352 threads = 11 warps, 64 points per block.
__global__ __launch_bounds__(352, 5) void hg_encode(
    const float*  __restrict__ coords,
    float*        __restrict__ out,
    int n_points)
{
    __shared__ float s_c[PTS * 3];
    __shared__ float s_out[PTS][33];

    const int tid   = threadIdx.x;
    const int lane  = tid & 31;
    const int warp  = tid >> 5;
    const int pbase = blockIdx.x * PTS;

    if (tid < PTS * 3) {
        const int g = pbase * 3 + tid;
        s_c[tid] = (g < n_points * 3) ? coords[g] : 0.0f;
    }
    __syncthreads();

    // ---------------- hashed level (all 11 warps, 2 point groups) ----------
    {
        const int level = warp + NDENSE;
        const float sc = c_scale[level];
        const unsigned* __restrict__ tb = g_half + ((size_t)warp << 19);
        const uint4*    __restrict__ tg = reinterpret_cast<const uint4*>(tb);

        #pragma unroll
        for (int grp = 0; grp < 2; ++grp) {
            const int pt = grp * 32 + lane;
            const float x = s_c[pt*3+0], y = s_c[pt*3+1], z = s_c[pt*3+2];

            const float px = x*sc + 0.5f, py = y*sc + 0.5f, pz = z*sc + 0.5f;
            const float fx = floorf(px), fy = floorf(py), fz = floorf(pz);
            const float wx = px - fx,    wy = py - fy,    wz = pz - fz;
            const unsigned gx = (unsigned)fx, gy = (unsigned)fy, gz = (unsigned)fz;

            const unsigned hy0 = gy * PRIME2, hy1 = hy0 + PRIME2;
            const unsigned hz0 = gz * PRIME3, hz1 = hz0 + PRIME3;
            // j = (dy,dz): 0=(0,0) 1=(0,1) 2=(1,0) 3=(1,1)
            const unsigned e0 = (gx ^ hy0 ^ hz0) & TMASK;
            const unsigned e1 = (gx ^ hy0 ^ hz1) & TMASK;
            const unsigned e2 = (gx ^ hy1 ^ hz0) & TMASK;
            const unsigned e3 = (gx ^ hy1 ^ hz1) & TMASK;
            const unsigned m  = gx ^ (gx + 1u);       // dx=1 corner: f = e ^ m
            const unsigned f0 = e0 ^ m, f1 = e1 ^ m, f2 = e2 ^ m, f3 = e3 ^ m;

            // aligned 16B group loads (issued back-to-back, MLP=4)
            const uint4 q0 = __ldg(tg + (e0 >> 2));
            const uint4 q1 = __ldg(tg + (e1 >> 2));
            const uint4 q2 = __ldg(tg + (e2 >> 2));
            const uint4 q3 = __ldg(tg + (e3 >> 2));

            unsigned b0, b1, b2, b3;
            if (m <= 3u) {
                // dx=1 corner in the same group (gx&3 != 3): register select
                b0 = ext4(q0, f0 & 3u);
                b1 = ext4(q1, f1 & 3u);
                b2 = ext4(q2, f2 & 3u);
                b3 = ext4(q3, f3 & 3u);
            } else {
                b0 = __ldg(tb + f0);
                b1 = __ldg(tb + f1);
                b2 = __ldg(tb + f2);
                b3 = __ldg(tb + f3);
            }
            const unsigned a0 = ext4(q0, e0 & 3u);
            const unsigned a1 = ext4(q1, e1 & 3u);
            const unsigned a2 = ext4(q2, e2 & 3u);
            const unsigned a3 = ext4(q3, e3 & 3u);

            const float2 va0 = __half22float2(*reinterpret_cast<const __half2*>(&a0));
            const float2 va1 = __half22float2(*reinterpret_cast<const __half2*>(&a1));
            const float2 va2 = __half22float2(*reinterpret_cast<const __half2*>(&a2));
            const float2 va3 = __half22float2(*reinterpret_cast<const __half2*>(&a3));
            const float2 vb0 = __half22float2(*reinterpret_cast<const __half2*>(&b0));
            const float2 vb1 = __half22float2(*reinterpret_cast<const __half2*>(&b1));
            const float2 vb2 = __half22float2(*reinterpret_cast<const __half2*>(&b2));
            const float2 vb3 = __half22float2(*reinterpret_cast<const __half2*>(&b3));

            const float ix = 1.0f - wx, iy = 1.0f - wy, iz = 1.0f - wz;
            const float a00 = ix*iy, a01 = ix*wy, a10 = wx*iy, a11 = wx*wy;
            const float w0 = a00*iz, w1 = a00*wz, w2 = a01*iz, w3 = a01*wz;
            const float w4 = a10*iz, w5 = a10*wz, w6 = a11*iz, w7 = a11*wz;

            float r0 = w0*va0.x;  float r1 = w0*va0.y;
            r0 += w1*va1.x;       r1 += w1*va1.y;
            r0 += w2*va2.x;       r1 += w2*va2.y;
            r0 += w3*va3.x;       r1 += w3*va3.y;
            r0 += w4*vb0.x;       r1 += w4*vb0.y;
            r0 += w5*vb1.x;       r1 += w5*vb1.y;
            r0 += w6*vb2.x;       r1 += w6*vb2.y;
            r0 += w7*vb3.x;       r1 += w7*vb3.y;

            s_out[pt][2*level + 0] = r0 * FINV;
            s_out[pt][2*level + 1] = r1 * FINV;
        }
    }

    // ---------------- dense levels: 1280 quad-tasks over all lanes ---------
    #pragma unroll
    for (int pass = 0; pass < 4; ++pass) {
        const int d = tid + pass * 352;
        if (d < 1280) {
            const int lvl = d >> 8;
            const int pt  = (d >> 2) & 63;
            const int k   = d & 3;           // dx=k>>1, dy=k&1

            const float    sc   = c_scale[lvl];
            const unsigned res  = c_res[lvl];
            const unsigned res2 = c_res2[lvl];
            const unsigned coff = c_coff[lvl];

            const float x = s_c[pt*3+0], y = s_c[pt*3+1], z = s_c[pt*3+2];
            const float px = x*sc + 0.5f, py = y*sc + 0.5f, pz = z*sc + 0.5f;
            const float fx = floorf(px), fy = floorf(py), fz = floorf(pz);
            const float wx = px - fx,    wy = py - fy,    wz = pz - fz;
            const unsigned gx = (unsigned)fx, gy = (unsigned)fy, gz = (unsigned)fz;

            const unsigned cell = coff + gx + gy*res + gz*res2;
            const float4 ch = __ldg(&g_cells[(size_t)cell * 4 + k]);  // quad: 1 line

            const float wdx = (k & 2) ? wx : 1.0f - wx;
            const float wdy = (k & 1) ? wy : 1.0f - wy;
            const float izz = 1.0f - wz;
            const float s   = wdx * wdy;
            float f0 = s * (izz*ch.x + wz*ch.z);
            float f1 = s * (izz*ch.y + wz*ch.w);

            f0 += __shfl_xor_sync(0xffffffffu, f0, 1);
            f1 += __shfl_xor_sync(0xffffffffu, f1, 1);
            f0 += __shfl_xor_sync(0xffffffffu, f0, 2);
            f1 += __shfl_xor_sync(0xffffffffu, f1, 2);

            if (k == 0) {
                s_out[pt][2*lvl + 0] = f0;
                s_out[pt][2*lvl + 1] = f1;
            }
        }
    }
    __syncthreads();

    // Coalesced writeback: 1024 float2 = 8KB contiguous per block.
    #pragma unroll
    for (int idx = tid; idx < PTS * 16; idx += 352) {
        const int pp = idx >> 4;
        const int c  = (idx & 15) * 2;
        const int gp = pbase + pp;
        if (gp < n_points) {
            const float a = s_out[pp][c];
            const float b = s_out[pp][c + 1];
            float2* o = reinterpret_cast<float2*>(out + (size_t)gp * 32 + c);
            *o = make_float2(a, b);
        }
    }
}

extern "C" void kernel_launch(void* const* d_in, const int* in_sizes, int n_in,
                              void* d_out, int out_size) {
    const float*  coords = (const float*)d_in[0];   // [N, 3] f32
    const float2* table  = (const float2*)d_in[1];  // [16, 2^19, 2] f32
    float*        out    = (float*)d_out;           // [N, 32] f32
    const int n_points = in_sizes[0] / 3;

    const unsigned nh = ((unsigned)NHASH << 19) / 4u;
    hg_to_half<<<(nh + 255) / 256, 256>>>(table);
    hg_repack<<<(TOTAL_CELLS + 255) / 256, 256>>>(table);
    const int blocks = (n_points + PTS - 1) / PTS;
    hg_encode<<<blocks, 352>>>(coords, out, n_points);
}

// round 9
// speedup vs baseline: 1.2341x; 1.2341x over previous
#include <cuda_runtime.h>
#include <cuda_fp16.h>
#include <stdint.h>

// ---------------------------------------------------------------------------
// tcnn HashGrid encode: coords [N,3] in [0,1], table [16, 2^19, 2] f32.
// Output [N, 32] f32. Levels 0-4 dense, 5-15 spatial-hashed.
//
// R9: fp16 grouped hashed gather, register-tight. Hashed levels stored as
// scaled (x4096) fp16x2 (4B/entry). Aligned LDG.128 covers 4 entries; with
// PRIME_x==1 the dx=1 corner f = e ^ (gx^(gx+1)) lies in the SAME 16B group
// for 75% of points -> avg 5 wavefronts/pt/lvl (was 6). R8's failure modes
// fixed: corner-pairs processed 2+2 (max two uint4 live -> no spills at the
// 37-reg/occ-5 budget) and the secondary load is a predicated ternary
// (@P LDG), not a per-lane branch.
// ---------------------------------------------------------------------------

namespace {
constexpr int      NLV    = 16;
constexpr int      NDENSE = 5;
constexpr int      NHASH  = 11;
constexpr unsigned TSZ    = 1u << 19;
constexpr unsigned TMASK  = TSZ - 1u;
constexpr unsigned PRIME2 = 2654435761u;
constexpr unsigned PRIME3 = 805459861u;
constexpr int      PTS    = 64;            // points per block
constexpr float    FSCL   = 4096.0f;       // fp16 storage scale
constexpr float    FINV   = 1.0f / 4096.0f;

constexpr double spow(int l) {
    double v = 1.0;
    for (int i = 0; i < l; ++i) v *= 1.4472692012786865;
    return v;
}
constexpr double scaled(int l) { return 16.0 * spow(l) - 1.0; }
constexpr unsigned resd(int l) {
    double sc = scaled(l);
    unsigned f = (unsigned)sc;
    return f + (((double)f < sc) ? 1u : 0u) + 1u;
}
constexpr unsigned cells_below(int l) {
    unsigned o = 0;
    for (int i = 0; i < l; ++i) o += resd(i) * resd(i) * resd(i);
    return o;
}
constexpr unsigned TOTAL_CELLS = cells_below(NDENSE);
static_assert(resd(0) == 16 && resd(4) == 71, "dense res sanity");
static_assert((unsigned long long)resd(4)*resd(4)*resd(4) <= TSZ, "lvl4 dense");
static_assert((unsigned long long)resd(5)*resd(5)*resd(5) >  TSZ, "lvl5 hashed");
static_assert(TOTAL_CELLS == 532784u, "cell count");
}

__constant__ float    c_scale[NLV] = {
    (float)scaled(0),(float)scaled(1),(float)scaled(2),(float)scaled(3),
    (float)scaled(4),(float)scaled(5),(float)scaled(6),(float)scaled(7),
    (float)scaled(8),(float)scaled(9),(float)scaled(10),(float)scaled(11),
    (float)scaled(12),(float)scaled(13),(float)scaled(14),(float)scaled(15)};
__constant__ unsigned c_res[NDENSE]  = {resd(0),resd(1),resd(2),resd(3),resd(4)};
__constant__ unsigned c_res2[NDENSE] = {resd(0)*resd(0),resd(1)*resd(1),
    resd(2)*resd(2),resd(3)*resd(3),resd(4)*resd(4)};
__constant__ unsigned c_coff[NDENSE] = {cells_below(0),cells_below(1),
    cells_below(2),cells_below(3),cells_below(4)};

__device__ __align__(128) float4   g_cells[(size_t)TOTAL_CELLS * 4];
__device__ __align__(128) unsigned g_half[(size_t)NHASH << 19];  // fp16x2 entries

// --- convert hashed levels to scaled fp16x2 (4 entries per thread).
__global__ void hg_to_half(const float2* __restrict__ table) {
    const unsigned n = (unsigned)NHASH << 19;
    const unsigned i = (blockIdx.x * blockDim.x + threadIdx.x) * 4u;
    if (i >= n) return;
    const float2* __restrict__ src = table + ((size_t)NDENSE << 19);
    uint4 o;
    {
        const float2 v = src[i + 0];
        const __half2 h = __floats2half2_rn(v.x * FSCL, v.y * FSCL);
        o.x = *reinterpret_cast<const unsigned*>(&h);
    }
    {
        const float2 v = src[i + 1];
        const __half2 h = __floats2half2_rn(v.x * FSCL, v.y * FSCL);
        o.y = *reinterpret_cast<const unsigned*>(&h);
    }
    {
        const float2 v = src[i + 2];
        const __half2 h = __floats2half2_rn(v.x * FSCL, v.y * FSCL);
        o.z = *reinterpret_cast<const unsigned*>(&h);
    }
    {
        const float2 v = src[i + 3];
        const __half2 h = __floats2half2_rn(v.x * FSCL, v.y * FSCL);
        o.w = *reinterpret_cast<const unsigned*>(&h);
    }
    *reinterpret_cast<uint4*>(g_half + i) = o;
}

// --- repack dense levels: cell (gx,gy,gz) -> 4 float4 = 8 corners (64B).
__global__ void hg_repack(const float2* __restrict__ table) {
    unsigned cid = blockIdx.x * blockDim.x + threadIdx.x;
    if (cid >= TOTAL_CELLS) return;

    int l = 0;
    #pragma unroll
    for (int i = 1; i < NDENSE; ++i) if (cid >= c_coff[i]) l = i;
    const unsigned res = c_res[l], res2 = c_res2[l];
    const unsigned local = cid - c_coff[l];
    const unsigned gz  = local / res2;
    const unsigned rem = local - gz * res2;
    const unsigned gy  = rem / res;
    const unsigned gx  = rem - gy * res;

    const unsigned R1  = res - 1u;
    const unsigned cx0 = gx,          cx1 = min(gx + 1u, R1);
    const unsigned cy0 = gy * res,    cy1 = min(gy + 1u, R1) * res;
    const unsigned cz0 = gz * res2,   cz1 = min(gz + 1u, R1) * res2;

    const float2* __restrict__ tbl = table + (size_t)l * (size_t)TSZ;
    float4* dst = &g_cells[(size_t)cid * 4];
    { float2 a = tbl[cx0+cy0+cz0], b = tbl[cx0+cy0+cz1]; dst[0]=make_float4(a.x,a.y,b.x,b.y); }
    { float2 a = tbl[cx0+cy1+cz0], b = tbl[cx0+cy1+cz1]; dst[1]=make_float4(a.x,a.y,b.x,b.y); }
    { float2 a = tbl[cx1+cy0+cz0], b = tbl[cx1+cy0+cz1]; dst[2]=make_float4(a.x,a.y,b.x,b.y); }
    { float2 a = tbl[cx1+cy1+cz0], b = tbl[cx1+cy1+cz1]; dst[3]=make_float4(a.x,a.y,b.x,b.y); }
}

// extract 32-bit word k (0..3) from a uint4
__device__ __forceinline__ unsigned ext4(const uint4& q, unsigned k) {
    return (k & 2u) ? ((k & 1u) ? q.w : q.z) : ((k & 1u) ? q.y : q.x);
}

// --- main encode. Block = 352 threads = 11 warps, 64 points per block.
__global__ __launch_bounds__(352, 5) void hg_encode(
    const float*  __restrict__ coords,
    float*        __restrict__ out,
    int n_points)
{
    __shared__ float s_c[PTS * 3];
    __shared__ float s_out[PTS][33];

    const int tid   = threadIdx.x;
    const int lane  = tid & 31;
    const int warp  = tid >> 5;
    const int pbase = blockIdx.x * PTS;

    if (tid < PTS * 3) {
        const int g = pbase * 3 + tid;
        s_c[tid] = (g < n_points * 3) ? coords[g] : 0.0f;
    }
    __syncthreads();

    // ---------------- hashed level (all 11 warps, 2 point groups) ----------
    {
        const int level = warp + NDENSE;
        const float sc = c_scale[level];
        const unsigned* __restrict__ tb = g_half + ((size_t)warp << 19);
        const uint4*    __restrict__ tg = reinterpret_cast<const uint4*>(tb);

        #pragma unroll
        for (int grp = 0; grp < 2; ++grp) {
            const int pt = grp * 32 + lane;
            const float x = s_c[pt*3+0], y = s_c[pt*3+1], z = s_c[pt*3+2];

            const float px = x*sc + 0.5f, py = y*sc + 0.5f, pz = z*sc + 0.5f;
            const float fx = floorf(px), fy = floorf(py), fz = floorf(pz);
            const float wx = px - fx,    wy = py - fy,    wz = pz - fz;
            const unsigned gx = (unsigned)fx, gy = (unsigned)fy, gz = (unsigned)fz;

            const unsigned hy0 = gy * PRIME2, hy1 = hy0 + PRIME2;
            const unsigned hz0 = gz * PRIME3, hz1 = hz0 + PRIME3;
            const unsigned m   = gx ^ (gx + 1u);       // dx=1 corner: f = e ^ m
            const bool   extra = (m > 3u);             // f outside 16B group (25%)

            // weights first (frees wx.. pressure early)
            const float ix = 1.0f - wx, iy = 1.0f - wy, iz = 1.0f - wz;
            const float a00 = ix*iy, a01 = ix*wy, a10 = wx*iy, a11 = wx*wy;
            const float w0 = a00*iz, w1 = a00*wz, w2 = a01*iz, w3 = a01*wz;
            const float w4 = a10*iz, w5 = a10*wz, w6 = a11*iz, w7 = a11*wz;

            float r0, r1;
            // ---- batch A: corner-pairs j=0 (dy0,dz0), j=1 (dy0,dz1) ----
            {
                const unsigned e0 = (gx ^ hy0 ^ hz0) & TMASK;
                const unsigned e1 = (gx ^ hy0 ^ hz1) & TMASK;
                const uint4 q0 = __ldg(tg + (e0 >> 2));
                const uint4 q1 = __ldg(tg + (e1 >> 2));
                const unsigned f0 = e0 ^ m, f1 = e1 ^ m;
                const unsigned xb0 = extra ? __ldg(tb + f0) : 0u;   // @P LDG
                const unsigned xb1 = extra ? __ldg(tb + f1) : 0u;
                const unsigned a0 = ext4(q0, e0 & 3u);
                const unsigned a1 = ext4(q1, e1 & 3u);
                const unsigned b0 = extra ? xb0 : ext4(q0, f0 & 3u);
                const unsigned b1 = extra ? xb1 : ext4(q1, f1 & 3u);
                const float2 va0 = __half22float2(*reinterpret_cast<const __half2*>(&a0));
                const float2 va1 = __half22float2(*reinterpret_cast<const __half2*>(&a1));
                const float2 vb0 = __half22float2(*reinterpret_cast<const __half2*>(&b0));
                const float2 vb1 = __half22float2(*reinterpret_cast<const __half2*>(&b1));
                r0  = w0*va0.x + w1*va1.x + w4*vb0.x + w5*vb1.x;
                r1  = w0*va0.y + w1*va1.y + w4*vb0.y + w5*vb1.y;
            }
            // ---- batch B: corner-pairs j=2 (dy1,dz0), j=3 (dy1,dz1) ----
            {
                const unsigned e2 = (gx ^ hy1 ^ hz0) & TMASK;
                const unsigned e3 = (gx ^ hy1 ^ hz1) & TMASK;
                const uint4 q2 = __ldg(tg + (e2 >> 2));
                const uint4 q3 = __ldg(tg + (e3 >> 2));
                const unsigned f2 = e2 ^ m, f3 = e3 ^ m;
                const unsigned xb2 = extra ? __ldg(tb + f2) : 0u;
                const unsigned xb3 = extra ? __ldg(tb + f3) : 0u;
                const unsigned a2 = ext4(q2, e2 & 3u);
                const unsigned a3 = ext4(q3, e3 & 3u);
                const unsigned b2 = extra ? xb2 : ext4(q2, f2 & 3u);
                const unsigned b3 = extra ? xb3 : ext4(q3, f3 & 3u);
                const float2 va2 = __half22float2(*reinterpret_cast<const __half2*>(&a2));
                const float2 va3 = __half22float2(*reinterpret_cast<const __half2*>(&a3));
                const float2 vb2 = __half22float2(*reinterpret_cast<const __half2*>(&b2));
                const float2 vb3 = __half22float2(*reinterpret_cast<const __half2*>(&b3));
                r0 += w2*va2.x + w3*va3.x + w6*vb2.x + w7*vb3.x;
                r1 += w2*va2.y + w3*va3.y + w6*vb2.y + w7*vb3.y;
            }

            s_out[pt][2*level + 0] = r0 * FINV;
            s_out[pt][2*level + 1] = r1 * FINV;
        }
    }

    // ---------------- dense levels: 1280 quad-tasks over all lanes ---------
    #pragma unroll
    for (int pass = 0; pass < 4; ++pass) {
        const int d = tid + pass * 352;
        if (d < 1280) {
            const int lvl = d >> 8;
            const int pt  = (d >> 2) & 63;
            const int k   = d & 3;           // dx=k>>1, dy=k&1

            const float    sc   = c_scale[lvl];
            const unsigned res  = c_res[lvl];
            const unsigned res2 = c_res2[lvl];
            const unsigned coff = c_coff[lvl];

            const float x = s_c[pt*3+0], y = s_c[pt*3+1], z = s_c[pt*3+2];
            const float px = x*sc + 0.5f, py = y*sc + 0.5f, pz = z*sc + 0.5f;
            const float fx = floorf(px), fy = floorf(py), fz = floorf(pz);
            const float wx = px - fx,    wy = py - fy,    wz = pz - fz;
            const unsigned gx = (unsigned)fx, gy = (unsigned)fy, gz = (unsigned)fz;

            const unsigned cell = coff + gx + gy*res + gz*res2;
            const float4 ch = __ldg(&g_cells[(size_t)cell * 4 + k]);  // quad: 1 line

            const float wdx = (k & 2) ? wx : 1.0f - wx;
            const float wdy = (k & 1) ? wy : 1.0f - wy;
            const float izz = 1.0f - wz;
            const float s   = wdx * wdy;
            float f0 = s * (izz*ch.x + wz*ch.z);
            float f1 = s * (izz*ch.y + wz*ch.w);

            f0 += __shfl_xor_sync(0xffffffffu, f0, 1);
            f1 += __shfl_xor_sync(0xffffffffu, f1, 1);
            f0 += __shfl_xor_sync(0xffffffffu, f0, 2);
            f1 += __shfl_xor_sync(0xffffffffu, f1, 2);

            if (k == 0) {
                s_out[pt][2*lvl + 0] = f0;
                s_out[pt][2*lvl + 1] = f1;
            }
        }
    }
    __syncthreads();

    // Coalesced writeback: 1024 float2 = 8KB contiguous per block.
    #pragma unroll
    for (int idx = tid; idx < PTS * 16; idx += 352) {
        const int pp = idx >> 4;
        const int c  = (idx & 15) * 2;
        const int gp = pbase + pp;
        if (gp < n_points) {
            const float a = s_out[pp][c];
            const float b = s_out[pp][c + 1];
            float2* o = reinterpret_cast<float2*>(out + (size_t)gp * 32 + c);
            *o = make_float2(a, b);
        }
    }
}

extern "C" void kernel_launch(void* const* d_in, const int* in_sizes, int n_in,
                              void* d_out, int out_size) {
    const float*  coords = (const float*)d_in[0];   // [N, 3] f32
    const float2* table  = (const float2*)d_in[1];  // [16, 2^19, 2] f32
    float*        out    = (float*)d_out;           // [N, 32] f32
    const int n_points = in_sizes[0] / 3;

    const unsigned nh = ((unsigned)NHASH << 19) / 4u;
    hg_to_half<<<(nh + 255) / 256, 256>>>(table);
    hg_repack<<<(TOTAL_CELLS + 255) / 256, 256>>>(table);
    const int blocks = (n_points + PTS - 1) / PTS;
    hg_encode<<<blocks, 352>>>(coords, out, n_points);
}